// round 9
// baseline (speedup 1.0000x reference)
#include <cuda_runtime.h>
#include <cstdint>
#include <cstddef>

#define NL  6
#define HN  256
#define GN  1024
#define IND 128
#define BN  128
#define TN  512
#define ON  10
#define CL  8

typedef unsigned long long ull;

// ---------------- scratch (static device globals: allowed) ----------------
__device__ float g_gx[(size_t)BN * TN * GN];        // 256 MB: per-layer input-GEMM result
__device__ float g_act[2][(size_t)BN * TN * HN];    // 2 x 64 MB: layer activations ping-pong

// ---------------- helpers ----------------
__device__ __forceinline__ ull fma2(ull a, ull b, ull c) {
    ull d;
    asm("fma.rn.f32x2 %0, %1, %2, %3;" : "=l"(d) : "l"(a), "l"(b), "l"(c));
    return d;
}
__device__ __forceinline__ float lo_f(ull v){ return __uint_as_float((unsigned)(v & 0xffffffffull)); }
__device__ __forceinline__ float hi_f(ull v){ return __uint_as_float((unsigned)(v >> 32)); }

__device__ __forceinline__ float sigm(float x){ return 1.f / (1.f + __expf(-x)); }
__device__ __forceinline__ float tanh_f(float x){
    float ax = fabsf(x);
    float e  = __expf(2.f * ax);          // inf-safe: 2/inf -> 0 -> r=1
    float r  = 1.f - 2.f / (e + 1.f);
    return copysignf(r, x);
}
__device__ __forceinline__ unsigned cluster_rank(){
    unsigned r; asm("mov.u32 %0, %%cluster_ctarank;" : "=r"(r)); return r;
}
__device__ __forceinline__ unsigned mapa_u32(unsigned a, unsigned r){
    unsigned d; asm("mapa.shared::cluster.u32 %0, %1, %2;" : "=r"(d) : "r"(a), "r"(r)); return d;
}

// ---------------- input GEMM: gx[m][n] = sum_k A[m][k]*Wih[n][k] + (bih[n]+bhh[n]) ----------------
// M = B*T = 65536, N = 1024, K = 256 (128 for layer 0). Tile 128(M) x 64(N), 256 threads,
// thread micro-tile 8x4, f32x2-packed along K (pairs are K-contiguous in SMEM -> direct LDS.64).
__global__ void __launch_bounds__(256) gx_gemm(
    const float* __restrict__ Aext, int inIdx, int lda, int K,
    const float* __restrict__ W,              // [GN][HN] row stride HN always
    const float* __restrict__ bih, const float* __restrict__ bhh)
{
    const float* A = Aext ? Aext : g_act[inIdx];
    __shared__ ull As[128 * 9];               // 128 rows x 8 k-pairs, padded to 9
    __shared__ ull Bs[64 * 9];

    const int tid = threadIdx.x;
    const int m0 = blockIdx.x * 128;
    const int n0 = blockIdx.y * 64;
    const int tx = tid & 15;                  // n group
    const int ty = tid >> 4;                  // m group

    ull acc[8][4] = {};

    const int nchunk = K >> 4;
    for (int kb = 0; kb < nchunk; kb++) {
        {   // load A tile: 128 rows x 16 floats (8 ull). 2 threads/row, 4 ull each.
            int row  = tid >> 1;
            const float* ga = A + (size_t)(m0 + row) * lda + kb * 16 + (tid & 1) * 8;
            ull* dst = &As[row * 9 + (tid & 1) * 4];
            #pragma unroll
            for (int q = 0; q < 4; q++) dst[q] = *(const ull*)(ga + q * 2);
        }
        if (tid < 128) {  // load W tile: 64 rows x 16 floats
            int rw = tid >> 1;
            const float* gb = W + (size_t)(n0 + rw) * HN + kb * 16 + (tid & 1) * 8;
            ull* db = &Bs[rw * 9 + (tid & 1) * 4];
            #pragma unroll
            for (int q = 0; q < 4; q++) db[q] = *(const ull*)(gb + q * 2);
        }
        __syncthreads();

        #pragma unroll
        for (int kp = 0; kp < 8; kp++) {
            ull b2[4];
            #pragma unroll
            for (int j = 0; j < 4; j++) b2[j] = Bs[(tx + 16 * j) * 9 + kp];
            #pragma unroll
            for (int i = 0; i < 8; i++) {
                ull a2 = As[(ty + 16 * i) * 9 + kp];
                #pragma unroll
                for (int j = 0; j < 4; j++) acc[i][j] = fma2(a2, b2[j], acc[i][j]);
            }
        }
        __syncthreads();
    }

    #pragma unroll
    for (int j = 0; j < 4; j++) {
        int n = n0 + tx + 16 * j;
        float bias = bih[n] + bhh[n];
        #pragma unroll
        for (int i = 0; i < 8; i++) {
            int m = m0 + ty + 16 * i;
            g_gx[(size_t)m * GN + n] = lo_f(acc[i][j]) + hi_f(acc[i][j]) + bias;
        }
    }
}

// ---------------- recurrent scan (one launch per layer) ----------------
// 16 clusters x 8 CTAs. Cluster c owns batch rows [8c, 8c+8). CTA rank r owns hidden
// units U = [32r, 32r+32) and keeps W_hh rows {q*256 + u : q in 0..3, u in U} in SMEM
// (fp32, 128KB), so the LSTM cell update for its units is fully local. Per step each
// CTA matvecs its 128 gate rows against the full h (SMEM, double-buffered), updates
// c/h for its 32 units, and broadcasts its h slice to all 8 CTAs via DSMEM.
#define SCAN_SMEM_FLOATS (32768 + 4096 + 1024 + 256)
#define SCAN_SMEM_BYTES  (SCAN_SMEM_FLOATS * 4)

__global__ void __cluster_dims__(CL, 1, 1) __launch_bounds__(256, 1)
lstm_scan(const float* __restrict__ whh,   // [GN][HN] for this layer
          const float* __restrict__ h0l,   // [BN][HN]
          const float* __restrict__ c0l,   // [BN][HN]
          int outIdx)
{
    extern __shared__ float sm[];
    float* Ws   = sm;                       // [128][256]  gate-row slice of W_hh
    float* hbuf = sm + 32768;               // [2][8][256] double-buffered h
    float* pre  = sm + 32768 + 4096;        // [8][128]    gate pre-activations (recurrent part)
    float* cst  = sm + 32768 + 4096 + 1024; // [8][32]     owned c state

    const int tid   = threadIdx.x;
    const unsigned rank = cluster_rank();   // 0..7
    const int cid   = blockIdx.x >> 3;      // 0..15
    const int bb    = cid * 8;              // first batch row

    // ---- load W slice: local gate-row lr = q*32 + ul  ->  global row q*256 + 32*rank + ul
    for (int li = tid; li < 128 * 256; li += 256) {
        int lr = li >> 8, k = li & 255;
        int q = lr >> 5, ul = lr & 31;
        Ws[li] = whh[(size_t)(q * HN + rank * 32 + ul) * HN + k];
    }
    // ---- init h, c
    #pragma unroll
    for (int i = 0; i < 8; i++) hbuf[i * HN + tid] = h0l[(size_t)(bb + i) * HN + tid];
    {
        int row = tid >> 5, u = tid & 31;
        cst[tid] = c0l[(size_t)(bb + row) * HN + rank * 32 + u];
    }
    __syncthreads();

    // DSMEM base address of hbuf in every cluster CTA (incl. self)
    unsigned hbase = (unsigned)__cvta_generic_to_shared(hbuf);
    unsigned rem[CL];
    #pragma unroll
    for (int d = 0; d < CL; d++) rem[d] = mapa_u32(hbase, (unsigned)d);

    const int row = tid >> 5, u = tid & 31;
    const int gu  = rank * 32 + u;          // global hidden unit this thread owns
    float* seq_out = g_act[outIdx];

    for (int t = 0; t < TN; t++) {
        const int cur = t & 1, nxt = cur ^ 1;

        // ---- matvec: threads 0..127, gate row lr = tid, 8 batch rows each, f32x2 packed
        if (tid < 128) {
            const ulonglong2* wp = (const ulonglong2*)(Ws + tid * 256);  // 64 x 16B
            const float* hb = hbuf + cur * 2048;
            ull acc[8] = {};
            #pragma unroll 4
            for (int kq = 0; kq < 64; kq++) {
                ulonglong2 w = wp[kq];
                #pragma unroll
                for (int r = 0; r < 8; r++) {
                    ulonglong2 h = ((const ulonglong2*)(hb + r * 256))[kq];
                    acc[r] = fma2(w.x, h.x, acc[r]);
                    acc[r] = fma2(w.y, h.y, acc[r]);
                }
            }
            #pragma unroll
            for (int r = 0; r < 8; r++)
                pre[r * 128 + tid] = lo_f(acc[r]) + hi_f(acc[r]);
        }
        __syncthreads();

        // ---- cell update: all 256 threads, one (batch row, unit) each
        {
            const float* gxr = g_gx + ((size_t)(bb + row) * TN + t) * GN;
            float gi = pre[row * 128      + u] + gxr[           gu];
            float gf = pre[row * 128 + 32 + u] + gxr[    HN   + gu];
            float gg = pre[row * 128 + 64 + u] + gxr[2 * HN   + gu];
            float go = pre[row * 128 + 96 + u] + gxr[3 * HN   + gu];

            float c = sigm(gf) * cst[tid] + sigm(gi) * tanh_f(gg);
            float h = sigm(go) * tanh_f(c);
            cst[tid] = c;

            unsigned off = (unsigned)((nxt * 2048 + row * HN + gu) * 4);
            #pragma unroll
            for (int d = 0; d < CL; d++)
                asm volatile("st.shared::cluster.f32 [%0], %1;"
                             :: "r"(rem[d] + off), "f"(h) : "memory");

            seq_out[((size_t)(bb + row) * TN + t) * HN + gu] = h;
        }

        // release own DSMEM writes / acquire peers' before next matvec
        asm volatile("barrier.cluster.arrive.aligned;" ::: "memory");
        asm volatile("barrier.cluster.wait.aligned;"   ::: "memory");
    }
}

// ---------------- final FC: out[b][o] = h_last[b] . fc_w[o] + fc_b[o] ----------------
__global__ void __launch_bounds__(256) fc_kernel(
    const float* __restrict__ fcw, const float* __restrict__ fcb,
    float* __restrict__ out)
{
    __shared__ float hs[HN];
    int b = blockIdx.x;
    const float* h = &g_act[(NL - 1) & 1][((size_t)b * TN + (TN - 1)) * HN];
    hs[threadIdx.x] = h[threadIdx.x];
    __syncthreads();
    if (threadIdx.x < ON) {
        int o = threadIdx.x;
        float s = fcb[o];
        #pragma unroll 8
        for (int u = 0; u < HN; u++) s += hs[u] * fcw[o * HN + u];
        out[b * ON + o] = s;
    }
}

// ---------------- launch ----------------
extern "C" void kernel_launch(void* const* d_in, const int* in_sizes, int n_in,
                              void* d_out, int out_size)
{
    (void)in_sizes; (void)n_in; (void)out_size;
    const float* x   = (const float*)d_in[0];
    const float* h0  = (const float*)d_in[1];
    const float* c0  = (const float*)d_in[2];
    const float* wih = (const float*)d_in[3];
    const float* whh = (const float*)d_in[4];
    const float* bih = (const float*)d_in[5];
    const float* bhh = (const float*)d_in[6];
    const float* fcw = (const float*)d_in[7];
    const float* fcb = (const float*)d_in[8];
    float* out = (float*)d_out;

    // idempotent, host-side, capture-safe
    cudaFuncSetAttribute(lstm_scan, cudaFuncAttributeMaxDynamicSharedMemorySize, SCAN_SMEM_BYTES);

    for (int l = 0; l < NL; l++) {
        const float* A = (l == 0) ? x : nullptr;
        int inIdx = (l == 0) ? 0 : ((l - 1) & 1);
        int lda   = (l == 0) ? IND : HN;
        dim3 grid(BN * TN / 128, GN / 64);
        gx_gemm<<<grid, 256>>>(A, inIdx, lda, lda,
                               wih + (size_t)l * GN * HN,
                               bih + (size_t)l * GN,
                               bhh + (size_t)l * GN);
        lstm_scan<<<128, 256, SCAN_SMEM_BYTES>>>(
            whh + (size_t)l * GN * HN,
            h0  + (size_t)l * BN * HN,
            c0  + (size_t)l * BN * HN,
            l & 1);
    }
    fc_kernel<<<BN, 256>>>(fcw, fcb, out);
}

// round 10
// speedup vs baseline: 1.8024x; 1.8024x over previous
#include <cuda_runtime.h>
#include <cstdint>
#include <cstddef>

#define NL  6
#define HN  256
#define GN  1024
#define IND 128
#define BN  128
#define TN  512
#define ON  10
#define CL  8

typedef unsigned long long ull;

// ---------------- scratch (static device globals: allowed) ----------------
__device__ float g_gx[(size_t)BN * TN * GN];        // 256 MB: per-layer input-GEMM result
__device__ float g_act[2][(size_t)BN * TN * HN];    // 2 x 64 MB: layer activations ping-pong

// ---------------- helpers ----------------
__device__ __forceinline__ ull fma2(ull a, ull b, ull c) {
    ull d;
    asm("fma.rn.f32x2 %0, %1, %2, %3;" : "=l"(d) : "l"(a), "l"(b), "l"(c));
    return d;
}
__device__ __forceinline__ float lo_f(ull v){ return __uint_as_float((unsigned)(v & 0xffffffffull)); }
__device__ __forceinline__ float hi_f(ull v){ return __uint_as_float((unsigned)(v >> 32)); }

__device__ __forceinline__ float sigm(float x){ return 1.f / (1.f + __expf(-x)); }
__device__ __forceinline__ float tanh_f(float x){
    float ax = fabsf(x);
    float e  = __expf(2.f * ax);          // inf-safe: 2/inf -> 0 -> r=1
    float r  = 1.f - 2.f / (e + 1.f);
    return copysignf(r, x);
}
__device__ __forceinline__ unsigned cluster_rank(){
    unsigned r; asm("mov.u32 %0, %%cluster_ctarank;" : "=r"(r)); return r;
}
__device__ __forceinline__ unsigned mapa_u32(unsigned a, unsigned r){
    unsigned d; asm("mapa.shared::cluster.u32 %0, %1, %2;" : "=r"(d) : "r"(a), "r"(r)); return d;
}

// ---------------- input GEMM: gx[m][n] = sum_k A[m][k]*Wih[n][k] + (bih[n]+bhh[n]) ----------------
// M = B*T = 65536, N = 1024, K = 256 (128 for layer 0). Tile 128(M) x 64(N), 256 threads,
// thread micro-tile 8x4, f32x2-packed along K.
__global__ void __launch_bounds__(256) gx_gemm(
    const float* __restrict__ Aext, int inIdx, int lda, int K,
    const float* __restrict__ W,              // [GN][HN] row stride HN always
    const float* __restrict__ bih, const float* __restrict__ bhh)
{
    const float* A = Aext ? Aext : g_act[inIdx];
    __shared__ ull As[128 * 9];               // 128 rows x 8 k-pairs, padded to 9
    __shared__ ull Bs[64 * 9];

    const int tid = threadIdx.x;
    const int m0 = blockIdx.x * 128;
    const int n0 = blockIdx.y * 64;
    const int tx = tid & 15;                  // n group
    const int ty = tid >> 4;                  // m group

    ull acc[8][4] = {};

    const int nchunk = K >> 4;
    for (int kb = 0; kb < nchunk; kb++) {
        {   // load A tile: 128 rows x 16 floats (8 ull). 2 threads/row, 4 ull each.
            int row  = tid >> 1;
            const float* ga = A + (size_t)(m0 + row) * lda + kb * 16 + (tid & 1) * 8;
            ull* dst = &As[row * 9 + (tid & 1) * 4];
            #pragma unroll
            for (int q = 0; q < 4; q++) dst[q] = *(const ull*)(ga + q * 2);
        }
        if (tid < 128) {  // load W tile: 64 rows x 16 floats
            int rw = tid >> 1;
            const float* gb = W + (size_t)(n0 + rw) * HN + kb * 16 + (tid & 1) * 8;
            ull* db = &Bs[rw * 9 + (tid & 1) * 4];
            #pragma unroll
            for (int q = 0; q < 4; q++) db[q] = *(const ull*)(gb + q * 2);
        }
        __syncthreads();

        #pragma unroll
        for (int kp = 0; kp < 8; kp++) {
            ull b2[4];
            #pragma unroll
            for (int j = 0; j < 4; j++) b2[j] = Bs[(tx + 16 * j) * 9 + kp];
            #pragma unroll
            for (int i = 0; i < 8; i++) {
                ull a2 = As[(ty + 16 * i) * 9 + kp];
                #pragma unroll
                for (int j = 0; j < 4; j++) acc[i][j] = fma2(a2, b2[j], acc[i][j]);
            }
        }
        __syncthreads();
    }

    #pragma unroll
    for (int j = 0; j < 4; j++) {
        int n = n0 + tx + 16 * j;
        float bias = bih[n] + bhh[n];
        #pragma unroll
        for (int i = 0; i < 8; i++) {
            int m = m0 + ty + 16 * i;
            g_gx[(size_t)m * GN + n] = lo_f(acc[i][j]) + hi_f(acc[i][j]) + bias;
        }
    }
}

// ---------------- recurrent scan (one launch per layer) ----------------
// 16 clusters x 8 CTAs, 512 threads/CTA. Cluster c owns batch rows [8c, 8c+8).
// CTA rank r owns hidden units [32r, 32r+32) and keeps its 128 gate rows of W_hh in
// SMEM in a bank-conflict-free [k4][gate_row] ulonglong2 layout (128 KB).
// Per step: thread (gr = tid&127, kq = tid>>7) computes a quarter-K partial dot for its
// gate row over all 8 batch rows (h broadcast from SMEM), partials summed in the cell
// update, h slice broadcast to all 8 CTAs via DSMEM, one cluster barrier per step.
#define SCAN_W_F    32768                     // Ws:   [64 k4][128 gr] x 4 floats
#define SCAN_H_F    4096                      // hbuf: [2][8][256]
#define SCAN_P_F    4096                      // pre:  [4 kq][8 row][128 gr]
#define SCAN_SMEM_FLOATS (SCAN_W_F + SCAN_H_F + SCAN_P_F + 256)
#define SCAN_SMEM_BYTES  (SCAN_SMEM_FLOATS * 4)

__global__ void __cluster_dims__(CL, 1, 1) __launch_bounds__(512, 1)
lstm_scan(const float* __restrict__ whh,   // [GN][HN] for this layer
          const float* __restrict__ h0l,   // [BN][HN]
          const float* __restrict__ c0l,   // [BN][HN]
          int outIdx)
{
    extern __shared__ float sm[];
    float* Ws   = sm;                                   // 128 KB, [k4*128+gr]*4
    float* hbuf = sm + SCAN_W_F;                        // [2][8][256]
    float* pre  = sm + SCAN_W_F + SCAN_H_F;             // [4][8][128]
    float* cst  = sm + SCAN_W_F + SCAN_H_F + SCAN_P_F;  // [8][32]

    const int tid   = threadIdx.x;
    const unsigned rank = cluster_rank();   // 0..7
    const int cid   = blockIdx.x >> 3;      // 0..15
    const int bb    = cid * 8;              // first batch row

    // ---- load W slice, conflict-free layout:
    // float index (k4*128 + gr)*4 + j  <-  whh[(q*256 + rank*32 + ul)*256 + 4*k4 + j]
    // with gr = q*32 + ul
    for (int li = tid; li < SCAN_W_F; li += 512) {
        int k4 = li >> 9;
        int rem = li & 511;
        int gr = rem >> 2, j = rem & 3;
        int q = gr >> 5, ul = gr & 31;
        Ws[li] = whh[(size_t)(q * HN + rank * 32 + ul) * HN + 4 * k4 + j];
    }
    // ---- init h (buffer 0), c
    for (int li = tid; li < 8 * HN; li += 512)
        hbuf[li] = h0l[(size_t)(bb + (li >> 8)) * HN + (li & 255)];
    if (tid < 256) {
        int row = tid >> 5, u = tid & 31;
        cst[tid] = c0l[(size_t)(bb + row) * HN + rank * 32 + u];
    }
    __syncthreads();

    // DSMEM base address of hbuf in every cluster CTA (incl. self)
    unsigned hbase = (unsigned)__cvta_generic_to_shared(hbuf);
    unsigned rem_a[CL];
    #pragma unroll
    for (int d = 0; d < CL; d++) rem_a[d] = mapa_u32(hbase, (unsigned)d);

    const int gr = tid & 127;               // gate row within slice
    const int kq = tid >> 7;                // k-quarter 0..3
    const int row = tid >> 5, u = tid & 31; // cell-update mapping (tid<256)
    const int gu  = rank * 32 + u;          // owned global hidden unit
    float* seq_out = g_act[outIdx];
    const float* gxp = (tid < 256)
        ? g_gx + (size_t)(bb + row) * TN * GN + gu : g_gx;

    const ulonglong2* wq = (const ulonglong2*)Ws + kq * 16 * 128 + gr;

    for (int t = 0; t < TN; t++) {
        const int cur = t & 1, nxt = cur ^ 1;

        // ---- prefetch this step's gx (hidden under the matvec)
        float gx0 = 0.f, gx1 = 0.f, gx2 = 0.f, gx3 = 0.f;
        if (tid < 256) {
            gx0 = __ldcs(gxp);
            gx1 = __ldcs(gxp + HN);
            gx2 = __ldcs(gxp + 2 * HN);
            gx3 = __ldcs(gxp + 3 * HN);
        }

        // ---- matvec partial: quarter-K dot of gate row gr against all 8 batch rows
        {
            const ulonglong2* hb = (const ulonglong2*)(hbuf + cur * 2048) + kq * 16;
            ull acc[8] = {};
            #pragma unroll 4
            for (int kk = 0; kk < 16; kk++) {
                ulonglong2 w = wq[(size_t)kk * 128];
                #pragma unroll
                for (int r = 0; r < 8; r++) {
                    ulonglong2 h = hb[r * 64 + kk];
                    acc[r] = fma2(w.x, h.x, acc[r]);
                    acc[r] = fma2(w.y, h.y, acc[r]);
                }
            }
            #pragma unroll
            for (int r = 0; r < 8; r++)
                pre[(kq * 8 + r) * 128 + gr] = lo_f(acc[r]) + hi_f(acc[r]);
        }
        __syncthreads();

        // ---- cell update: threads 0..255, one (batch row, unit) each
        if (tid < 256) {
            float gi = gx0, gf = gx1, gg = gx2, go = gx3;
            #pragma unroll
            for (int p = 0; p < 4; p++) {
                const float* pr = pre + (p * 8 + row) * 128;
                gi += pr[u];
                gf += pr[32 + u];
                gg += pr[64 + u];
                go += pr[96 + u];
            }
            float c = sigm(gf) * cst[tid] + sigm(gi) * tanh_f(gg);
            float h = sigm(go) * tanh_f(c);
            cst[tid] = c;

            unsigned off = (unsigned)((nxt * 2048 + row * HN + gu) * 4);
            #pragma unroll
            for (int d = 0; d < CL; d++)
                asm volatile("st.shared::cluster.f32 [%0], %1;"
                             :: "r"(rem_a[d] + off), "f"(h) : "memory");

            seq_out[((size_t)(bb + row) * TN + t) * HN + gu] = h;
            gxp += GN;
        }

        // release own DSMEM writes / acquire peers' before next matvec
        asm volatile("barrier.cluster.arrive.aligned;" ::: "memory");
        asm volatile("barrier.cluster.wait.aligned;"   ::: "memory");
    }
}

// ---------------- final FC: out[b][o] = h_last[b] . fc_w[o] + fc_b[o] ----------------
__global__ void __launch_bounds__(256) fc_kernel(
    const float* __restrict__ fcw, const float* __restrict__ fcb,
    float* __restrict__ out)
{
    __shared__ float hs[HN];
    int b = blockIdx.x;
    const float* h = &g_act[(NL - 1) & 1][((size_t)b * TN + (TN - 1)) * HN];
    hs[threadIdx.x] = h[threadIdx.x];
    __syncthreads();
    if (threadIdx.x < ON) {
        int o = threadIdx.x;
        float s = fcb[o];
        #pragma unroll 8
        for (int u = 0; u < HN; u++) s += hs[u] * fcw[o * HN + u];
        out[b * ON + o] = s;
    }
}

// ---------------- launch ----------------
extern "C" void kernel_launch(void* const* d_in, const int* in_sizes, int n_in,
                              void* d_out, int out_size)
{
    (void)in_sizes; (void)n_in; (void)out_size;
    const float* x   = (const float*)d_in[0];
    const float* h0  = (const float*)d_in[1];
    const float* c0  = (const float*)d_in[2];
    const float* wih = (const float*)d_in[3];
    const float* whh = (const float*)d_in[4];
    const float* bih = (const float*)d_in[5];
    const float* bhh = (const float*)d_in[6];
    const float* fcw = (const float*)d_in[7];
    const float* fcb = (const float*)d_in[8];
    float* out = (float*)d_out;

    // idempotent, host-side, capture-safe
    cudaFuncSetAttribute(lstm_scan, cudaFuncAttributeMaxDynamicSharedMemorySize, SCAN_SMEM_BYTES);

    for (int l = 0; l < NL; l++) {
        const float* A = (l == 0) ? x : nullptr;
        int inIdx = (l == 0) ? 0 : ((l - 1) & 1);
        int lda   = (l == 0) ? IND : HN;
        dim3 grid(BN * TN / 128, GN / 64);
        gx_gemm<<<grid, 256>>>(A, inIdx, lda, lda,
                               wih + (size_t)l * GN * HN,
                               bih + (size_t)l * GN,
                               bhh + (size_t)l * GN);
        lstm_scan<<<128, 512, SCAN_SMEM_BYTES>>>(
            whh + (size_t)l * GN * HN,
            h0  + (size_t)l * BN * HN,
            c0  + (size_t)l * BN * HN,
            l & 1);
    }
    fc_kernel<<<BN, 256>>>(fcw, fcb, out);
}

// round 12
// speedup vs baseline: 1.8937x; 1.0507x over previous
#include <cuda_runtime.h>
#include <cstdint>
#include <cstddef>

#define NL  6
#define HN  256
#define GN  1024
#define IND 128
#define BN  128
#define TN  512
#define ON  10
#define CL  8

typedef unsigned long long ull;

// ---------------- scratch (static device globals: allowed) ----------------
__device__ float g_gx[(size_t)BN * TN * GN];        // 256 MB: per-layer input-GEMM result
__device__ float g_act[2][(size_t)BN * TN * HN];    // 2 x 64 MB: layer activations ping-pong

// ---------------- helpers ----------------
__device__ __forceinline__ ull fma2(ull a, ull b, ull c) {
    ull d;
    asm("fma.rn.f32x2 %0, %1, %2, %3;" : "=l"(d) : "l"(a), "l"(b), "l"(c));
    return d;
}
__device__ __forceinline__ float lo_f(ull v){ return __uint_as_float((unsigned)(v & 0xffffffffull)); }
__device__ __forceinline__ float hi_f(ull v){ return __uint_as_float((unsigned)(v >> 32)); }

__device__ __forceinline__ float sigm(float x){ return 1.f / (1.f + __expf(-x)); }
__device__ __forceinline__ float tanh_f(float x){
    float ax = fabsf(x);
    float e  = __expf(2.f * ax);          // inf-safe: 2/inf -> 0 -> r=1
    float r  = 1.f - 2.f / (e + 1.f);
    return copysignf(r, x);
}
__device__ __forceinline__ unsigned cluster_rank(){
    unsigned r; asm("mov.u32 %0, %%cluster_ctarank;" : "=r"(r)); return r;
}
__device__ __forceinline__ unsigned mapa_u32(unsigned a, unsigned r){
    unsigned d; asm("mapa.shared::cluster.u32 %0, %1, %2;" : "=r"(d) : "r"(a), "r"(r)); return d;
}

// ---------------- input GEMM: gx[m][n] = sum_k A[m][k]*Wih[n][k] + (bih[n]+bhh[n]) ----------------
__global__ void __launch_bounds__(256) gx_gemm(
    const float* __restrict__ Aext, int inIdx, int lda, int K,
    const float* __restrict__ W,              // [GN][HN] row stride HN always
    const float* __restrict__ bih, const float* __restrict__ bhh)
{
    const float* A = Aext ? Aext : g_act[inIdx];
    __shared__ ull As[128 * 9];               // 128 rows x 8 k-pairs, padded to 9
    __shared__ ull Bs[64 * 9];

    const int tid = threadIdx.x;
    const int m0 = blockIdx.x * 128;
    const int n0 = blockIdx.y * 64;
    const int tx = tid & 15;                  // n group
    const int ty = tid >> 4;                  // m group

    ull acc[8][4] = {};

    const int nchunk = K >> 4;
    for (int kb = 0; kb < nchunk; kb++) {
        {   // load A tile: 128 rows x 16 floats (8 ull). 2 threads/row, 4 ull each.
            int row  = tid >> 1;
            const float* ga = A + (size_t)(m0 + row) * lda + kb * 16 + (tid & 1) * 8;
            ull* dst = &As[row * 9 + (tid & 1) * 4];
            #pragma unroll
            for (int q = 0; q < 4; q++) dst[q] = *(const ull*)(ga + q * 2);
        }
        if (tid < 128) {  // load W tile: 64 rows x 16 floats
            int rw = tid >> 1;
            const float* gb = W + (size_t)(n0 + rw) * HN + kb * 16 + (tid & 1) * 8;
            ull* db = &Bs[rw * 9 + (tid & 1) * 4];
            #pragma unroll
            for (int q = 0; q < 4; q++) db[q] = *(const ull*)(gb + q * 2);
        }
        __syncthreads();

        #pragma unroll
        for (int kp = 0; kp < 8; kp++) {
            ull b2[4];
            #pragma unroll
            for (int j = 0; j < 4; j++) b2[j] = Bs[(tx + 16 * j) * 9 + kp];
            #pragma unroll
            for (int i = 0; i < 8; i++) {
                ull a2 = As[(ty + 16 * i) * 9 + kp];
                #pragma unroll
                for (int j = 0; j < 4; j++) acc[i][j] = fma2(a2, b2[j], acc[i][j]);
            }
        }
        __syncthreads();
    }

    #pragma unroll
    for (int j = 0; j < 4; j++) {
        int n = n0 + tx + 16 * j;
        float bias = bih[n] + bhh[n];
        #pragma unroll
        for (int i = 0; i < 8; i++) {
            int m = m0 + ty + 16 * i;
            g_gx[(size_t)m * GN + n] = lo_f(acc[i][j]) + hi_f(acc[i][j]) + bias;
        }
    }
}

// ---------------- recurrent scan (one launch per layer) ----------------
// 16 clusters x 8 CTAs, 1024 threads/CTA. Cluster c owns batch rows [8c,8c+8).
// CTA rank r owns hidden units [32r,32r+32); its 128 gate rows of W_hh live in SMEM
// as [kk(64)][r2(2)][g2(64)] ulonglong2 (lane-dense 16B stride, conflict-free).
// Per step: thread (kq = tid>>6 in 0..15, g2 = tid&63) computes a 16-float-K partial
// dot of gate rows {2g2, 2g2+1} against all 8 batch rows (h broadcast from SMEM);
// stage-1: 1024 threads reduce the 16 k-partials per (row, gate-row); stage-2: 256
// threads apply activations, update c, and broadcast packed h pairs to all 8 CTAs
// via DSMEM; one cluster barrier per step (release orders the remote stores).
#define SCAN_W_F   32768                      // Ws
#define SCAN_H_F   4096                       // hbuf [2][8][256]
#define SCAN_P_F   16384                      // pre  [16 kq][8 row][128 gr]
#define SCAN_R_F   1024                       // red  [8 row][128 gr]
#define SCAN_SMEM_FLOATS (SCAN_W_F + SCAN_H_F + SCAN_P_F + SCAN_R_F + 256)
#define SCAN_SMEM_BYTES  (SCAN_SMEM_FLOATS * 4)

__global__ void __cluster_dims__(CL, 1, 1) __launch_bounds__(1024, 1)
lstm_scan(const float* __restrict__ whh,   // [GN][HN] for this layer
          const float* __restrict__ h0l,   // [BN][HN]
          const float* __restrict__ c0l,   // [BN][HN]
          int outIdx)
{
    extern __shared__ float sm[];
    float* Ws   = sm;                                   // 128 KB
    float* hbuf = sm + SCAN_W_F;                        // [2][8][256]
    float* pre  = hbuf + SCAN_H_F;                      // [16][8][128]
    float* red  = pre + SCAN_P_F;                       // [8][128]
    float* cst  = red + SCAN_R_F;                       // [256]

    const int tid   = threadIdx.x;
    const unsigned rank = cluster_rank();   // 0..7
    const int cid   = blockIdx.x >> 3;      // 0..15
    const int bb    = cid * 8;              // first batch row

    // ---- load W slice: float li -> ull2 u2 = (kk*2 + r2)*64 + g2, j = li&3
    // holds whh[(q*256 + rank*32 + ul)][4kk + j] with gr = 2*g2 + r2, q = gr>>5, ul = gr&31
    for (int li = tid; li < SCAN_W_F; li += 1024) {
        int j  = li & 3;
        int u2 = li >> 2;
        int g2 = u2 & 63;
        int r2 = (u2 >> 6) & 1;
        int kk = u2 >> 7;
        int gr = 2 * g2 + r2, q = gr >> 5, ul = gr & 31;
        Ws[li] = whh[(size_t)(q * HN + rank * 32 + ul) * HN + 4 * kk + j];
    }
    // ---- init h (buffer 0), c
    for (int li = tid; li < 8 * HN; li += 1024)
        hbuf[li] = h0l[(size_t)(bb + (li >> 8)) * HN + (li & 255)];
    if (tid < 256) {
        int row = tid >> 5, u = tid & 31;
        cst[tid] = c0l[(size_t)(bb + row) * HN + rank * 32 + u];
    }
    __syncthreads();

    const unsigned hbase = (unsigned)__cvta_generic_to_shared(hbuf);

    const int kq  = tid >> 6;               // 0..15, warp-uniform
    const int g2  = tid & 63;
    const int r1  = tid >> 7, gr1 = tid & 127;   // stage-1 mapping
    const int row = tid >> 5, u = tid & 31;      // stage-2 mapping (tid<256)
    const int gu  = rank * 32 + u;
    float* seq_out = g_act[outIdx];
    const float* gxp = (tid < 256)
        ? g_gx + (size_t)(bb + row) * TN * GN + gu : g_gx;

    const ulonglong2* wbase = (const ulonglong2*)Ws + g2;

    for (int t = 0; t < TN; t++) {
        const int cur = t & 1, nxt = cur ^ 1;

        // ---- prefetch this step's gx (hidden under the matvec)
        float gx0 = 0.f, gx1 = 0.f, gx2 = 0.f, gx3 = 0.f;
        if (tid < 256) {
            gx0 = __ldcs(gxp);
            gx1 = __ldcs(gxp + HN);
            gx2 = __ldcs(gxp + 2 * HN);
            gx3 = __ldcs(gxp + 3 * HN);
        }

        // ---- matvec partial: gate rows {2g2, 2g2+1}, K slice [16kq, 16kq+16), 8 rows
        {
            const ulonglong2* hb = (const ulonglong2*)(hbuf + cur * 2048);
            ull a0[8] = {}, a1[8] = {};
            #pragma unroll
            for (int j = 0; j < 4; j++) {
                const int kk = kq * 4 + j;
                ulonglong2 w0 = wbase[(kk * 2    ) * 64];
                ulonglong2 w1 = wbase[(kk * 2 + 1) * 64];
                #pragma unroll
                for (int r = 0; r < 8; r++) {
                    ulonglong2 h = hb[r * 64 + kk];   // warp-broadcast
                    a0[r] = fma2(w0.x, h.x, a0[r]);
                    a0[r] = fma2(w0.y, h.y, a0[r]);
                    a1[r] = fma2(w1.x, h.x, a1[r]);
                    a1[r] = fma2(w1.y, h.y, a1[r]);
                }
            }
            #pragma unroll
            for (int r = 0; r < 8; r++) {
                float p0 = lo_f(a0[r]) + hi_f(a0[r]);
                float p1 = lo_f(a1[r]) + hi_f(a1[r]);
                ull pk = ((ull)__float_as_uint(p1) << 32) | (ull)__float_as_uint(p0);
                *(ull*)&pre[(kq * 8 + r) * 128 + 2 * g2] = pk;   // STS.64, dense
            }
        }
        __syncthreads();

        // ---- stage 1: reduce 16 k-partials; all 1024 threads, one (row, gate row) each
        {
            const float* pp = pre + r1 * 128 + gr1;
            float s = 0.f;
            #pragma unroll
            for (int p = 0; p < 16; p++) s += pp[p * 1024];
            red[r1 * 128 + gr1] = s;
        }
        __syncthreads();

        // ---- stage 2: activations + state update + DSMEM broadcast (tid<256)
        if (tid < 256) {
            const float* rr = red + row * 128;
            float gi = gx0 + rr[u];
            float gf = gx1 + rr[32 + u];
            float gg = gx2 + rr[64 + u];
            float go = gx3 + rr[96 + u];

            float c = sigm(gf) * cst[tid] + sigm(gi) * tanh_f(gg);
            float h = sigm(go) * tanh_f(c);
            cst[tid] = c;

            seq_out[((size_t)(bb + row) * TN + t) * HN + gu] = h;

            // pack (h_u, h_{u+1}) in even lanes, one 64-bit remote store per CTA
            float hup = __shfl_down_sync(0xffffffffu, h, 1);
            if ((tid & 1) == 0) {
                ull hv = ((ull)__float_as_uint(hup) << 32) | (ull)__float_as_uint(h);
                unsigned off = (unsigned)((nxt * 2048 + row * HN + gu) * 4);
                #pragma unroll
                for (int d = 0; d < CL; d++) {
                    unsigned ra = mapa_u32(hbase, (unsigned)d) + off;
                    asm volatile("st.shared::cluster.b64 [%0], %1;"
                                 :: "r"(ra), "l"(hv) : "memory");
                }
            }
            gxp += GN;
        }

        // release own DSMEM writes / acquire peers' before next matvec
        asm volatile("barrier.cluster.arrive.aligned;" ::: "memory");
        asm volatile("barrier.cluster.wait.aligned;"   ::: "memory");
    }
}

// ---------------- final FC: out[b][o] = h_last[b] . fc_w[o] + fc_b[o] ----------------
__global__ void __launch_bounds__(256) fc_kernel(
    const float* __restrict__ fcw, const float* __restrict__ fcb,
    float* __restrict__ out)
{
    __shared__ float hs[HN];
    int b = blockIdx.x;
    const float* h = &g_act[(NL - 1) & 1][((size_t)b * TN + (TN - 1)) * HN];
    hs[threadIdx.x] = h[threadIdx.x];
    __syncthreads();
    if (threadIdx.x < ON) {
        int o = threadIdx.x;
        float s = fcb[o];
        #pragma unroll 8
        for (int u = 0; u < HN; u++) s += hs[u] * fcw[o * HN + u];
        out[b * ON + o] = s;
    }
}

// ---------------- launch ----------------
extern "C" void kernel_launch(void* const* d_in, const int* in_sizes, int n_in,
                              void* d_out, int out_size)
{
    (void)in_sizes; (void)n_in; (void)out_size;
    const float* x   = (const float*)d_in[0];
    const float* h0  = (const float*)d_in[1];
    const float* c0  = (const float*)d_in[2];
    const float* wih = (const float*)d_in[3];
    const float* whh = (const float*)d_in[4];
    const float* bih = (const float*)d_in[5];
    const float* bhh = (const float*)d_in[6];
    const float* fcw = (const float*)d_in[7];
    const float* fcb = (const float*)d_in[8];
    float* out = (float*)d_out;

    // idempotent, host-side, capture-safe
    cudaFuncSetAttribute(lstm_scan, cudaFuncAttributeMaxDynamicSharedMemorySize, SCAN_SMEM_BYTES);

    for (int l = 0; l < NL; l++) {
        const float* A = (l == 0) ? x : nullptr;
        int inIdx = (l == 0) ? 0 : ((l - 1) & 1);
        int lda   = (l == 0) ? IND : HN;
        dim3 grid(BN * TN / 128, GN / 64);
        gx_gemm<<<grid, 256>>>(A, inIdx, lda, lda,
                               wih + (size_t)l * GN * HN,
                               bih + (size_t)l * GN,
                               bhh + (size_t)l * GN);
        lstm_scan<<<128, 1024, SCAN_SMEM_BYTES>>>(
            whh + (size_t)l * GN * HN,
            h0  + (size_t)l * BN * HN,
            c0  + (size_t)l * BN * HN,
            l & 1);
    }
    fc_kernel<<<BN, 256>>>(fcw, fcb, out);
}

// round 13
// speedup vs baseline: 2.0388x; 1.0766x over previous
#include <cuda_runtime.h>
#include <cstdint>
#include <cstddef>

#define NL  6
#define HN  256
#define GN  1024
#define IND 128
#define BN  128
#define TN  512
#define ON  10
#define CL  8

typedef unsigned long long ull;

// ---------------- scratch (static device globals: allowed) ----------------
__device__ float g_gx[(size_t)BN * TN * GN];        // 256 MB: per-layer input-GEMM result
__device__ float g_act[2][(size_t)BN * TN * HN];    // 2 x 64 MB: layer activations ping-pong

// ---------------- helpers ----------------
__device__ __forceinline__ ull fma2(ull a, ull b, ull c) {
    ull d;
    asm("fma.rn.f32x2 %0, %1, %2, %3;" : "=l"(d) : "l"(a), "l"(b), "l"(c));
    return d;
}
__device__ __forceinline__ float lo_f(ull v){ return __uint_as_float((unsigned)(v & 0xffffffffull)); }
__device__ __forceinline__ float hi_f(ull v){ return __uint_as_float((unsigned)(v >> 32)); }

__device__ __forceinline__ float sigm(float x){ return 1.f / (1.f + __expf(-x)); }
__device__ __forceinline__ float tanh_f(float x){
    float ax = fabsf(x);
    float e  = __expf(2.f * ax);          // inf-safe: 2/inf -> 0 -> r=1
    float r  = 1.f - 2.f / (e + 1.f);
    return copysignf(r, x);
}
__device__ __forceinline__ unsigned cluster_rank(){
    unsigned r; asm("mov.u32 %0, %%cluster_ctarank;" : "=r"(r)); return r;
}
__device__ __forceinline__ unsigned mapa_u32(unsigned a, unsigned r){
    unsigned d; asm("mapa.shared::cluster.u32 %0, %1, %2;" : "=r"(d) : "r"(a), "r"(r)); return d;
}
__device__ __forceinline__ unsigned smem_u32(const void* p){
    return (unsigned)__cvta_generic_to_shared(p);
}
__device__ __forceinline__ void cpa4(unsigned dst, const float* src){
    asm volatile("cp.async.ca.shared.global [%0], [%1], 4;" :: "r"(dst), "l"(src) : "memory");
}

// ---------------- input GEMM: gx[m][n] = sum_k A[m][k]*Wih[n][k] + (bih[n]+bhh[n]) ----------------
__global__ void __launch_bounds__(256) gx_gemm(
    const float* __restrict__ Aext, int inIdx, int lda, int K,
    const float* __restrict__ W,              // [GN][HN] row stride HN always
    const float* __restrict__ bih, const float* __restrict__ bhh)
{
    const float* A = Aext ? Aext : g_act[inIdx];
    __shared__ ull As[128 * 9];               // 128 rows x 8 k-pairs, padded to 9
    __shared__ ull Bs[64 * 9];

    const int tid = threadIdx.x;
    const int m0 = blockIdx.x * 128;
    const int n0 = blockIdx.y * 64;
    const int tx = tid & 15;                  // n group
    const int ty = tid >> 4;                  // m group

    ull acc[8][4] = {};

    const int nchunk = K >> 4;
    for (int kb = 0; kb < nchunk; kb++) {
        {   // load A tile: 128 rows x 16 floats (8 ull). 2 threads/row, 4 ull each.
            int row  = tid >> 1;
            const float* ga = A + (size_t)(m0 + row) * lda + kb * 16 + (tid & 1) * 8;
            ull* dst = &As[row * 9 + (tid & 1) * 4];
            #pragma unroll
            for (int q = 0; q < 4; q++) dst[q] = *(const ull*)(ga + q * 2);
        }
        if (tid < 128) {  // load W tile: 64 rows x 16 floats
            int rw = tid >> 1;
            const float* gb = W + (size_t)(n0 + rw) * HN + kb * 16 + (tid & 1) * 8;
            ull* db = &Bs[rw * 9 + (tid & 1) * 4];
            #pragma unroll
            for (int q = 0; q < 4; q++) db[q] = *(const ull*)(gb + q * 2);
        }
        __syncthreads();

        #pragma unroll
        for (int kp = 0; kp < 8; kp++) {
            ull b2[4];
            #pragma unroll
            for (int j = 0; j < 4; j++) b2[j] = Bs[(tx + 16 * j) * 9 + kp];
            #pragma unroll
            for (int i = 0; i < 8; i++) {
                ull a2 = As[(ty + 16 * i) * 9 + kp];
                #pragma unroll
                for (int j = 0; j < 4; j++) acc[i][j] = fma2(a2, b2[j], acc[i][j]);
            }
        }
        __syncthreads();
    }

    #pragma unroll
    for (int j = 0; j < 4; j++) {
        int n = n0 + tx + 16 * j;
        float bias = bih[n] + bhh[n];
        #pragma unroll
        for (int i = 0; i < 8; i++) {
            int m = m0 + ty + 16 * i;
            g_gx[(size_t)m * GN + n] = lo_f(acc[i][j]) + hi_f(acc[i][j]) + bias;
        }
    }
}

// ---------------- recurrent scan (one launch per layer) ----------------
// 16 clusters x 8 CTAs, 1024 threads/CTA. Cluster c owns batch rows [8c,8c+8).
// CTA rank r owns hidden units [32r,32r+32); its 128 gate rows of W_hh live in SMEM
// as [kk(64)][r2(2)][g2(64)] ulonglong2 (lane-dense 16B stride, conflict-free).
// Per step:
//   - cp.async prefetch of this step's gx into SMEM (no regs held, DRAM hidden)
//   - mbarrier wait (count 64, phase parity): all peers' h(t-1) slices arrived
//   - matvec: thread (kq=tid>>6, g2=tid&63) -> 16-float-K partial dot of gate rows
//     {2g2,2g2+1} against 8 batch rows; partials to pre[16][8][128]
//   - __syncthreads
//   - stage2 (tid<256): sum 16 partials + gx, activations, c/h update; h pairs
//     broadcast to all 8 CTAs via st.shared::cluster.b64; per-warp
//     fence.acq_rel.cluster + remote mbarrier arrive (8 warps x 8 CTAs = 64)
//   - __syncthreads (protects pre for next matvec)
// No full cluster rendezvous per step; final cluster sync only at kernel exit.
#define SCAN_W_F   32768                      // Ws
#define SCAN_H_F   4096                       // hbuf [2][8][256]
#define SCAN_P_F   16384                      // pre  [16 kq][8 row][128 gr]
#define SCAN_G_F   1024                       // gxs  [256 threads][4 gates]
#define SCAN_C_F   256                        // cst
#define SCAN_SMEM_FLOATS (SCAN_W_F + SCAN_H_F + SCAN_P_F + SCAN_G_F + SCAN_C_F + 8)
#define SCAN_SMEM_BYTES  (SCAN_SMEM_FLOATS * 4)

__global__ void __cluster_dims__(CL, 1, 1) __launch_bounds__(1024, 1)
lstm_scan(const float* __restrict__ whh,   // [GN][HN] for this layer
          const float* __restrict__ h0l,   // [BN][HN]
          const float* __restrict__ c0l,   // [BN][HN]
          int outIdx)
{
    extern __shared__ float sm[];
    float* Ws   = sm;                                   // 128 KB
    float* hbuf = sm + SCAN_W_F;                        // [2][8][256]
    float* pre  = hbuf + SCAN_H_F;                      // [16][8][128]
    float* gxs  = pre + SCAN_P_F;                       // [256][4]
    float* cst  = gxs + SCAN_G_F;                       // [256]
    // mbarrier lives right after cst (8-byte aligned: offset 54528 floats)
    const unsigned mbar = smem_u32(cst + SCAN_C_F);
    const unsigned hbase = smem_u32(hbuf);
    const unsigned gxbase = smem_u32(gxs);

    const int tid   = threadIdx.x;
    const unsigned rank = cluster_rank();   // 0..7
    const int cid   = blockIdx.x >> 3;      // 0..15
    const int bb    = cid * 8;              // first batch row

    // ---- init mbarrier (count = 8 warps x 8 CTAs = 64 arrivals per step)
    if (tid == 0)
        asm volatile("mbarrier.init.shared.b64 [%0], %1;" :: "r"(mbar), "r"(64) : "memory");

    // ---- load W slice: float li -> ull2 u2 = (kk*2 + r2)*64 + g2, j = li&3
    // holds whh[(q*256 + rank*32 + ul)][4kk + j] with gr = 2*g2 + r2, q = gr>>5, ul = gr&31
    for (int li = tid; li < SCAN_W_F; li += 1024) {
        int j  = li & 3;
        int u2 = li >> 2;
        int g2 = u2 & 63;
        int r2 = (u2 >> 6) & 1;
        int kk = u2 >> 7;
        int gr = 2 * g2 + r2, q = gr >> 5, ul = gr & 31;
        Ws[li] = whh[(size_t)(q * HN + rank * 32 + ul) * HN + 4 * kk + j];
    }
    // ---- init h (buffer 0), c
    for (int li = tid; li < 8 * HN; li += 1024)
        hbuf[li] = h0l[(size_t)(bb + (li >> 8)) * HN + (li & 255)];
    if (tid < 256) {
        int row = tid >> 5, u = tid & 31;
        cst[tid] = c0l[(size_t)(bb + row) * HN + rank * 32 + u];
    }
    __syncthreads();
    // cluster sync: all mbarriers initialized before any remote arrive can land
    asm volatile("barrier.cluster.arrive.aligned;" ::: "memory");
    asm volatile("barrier.cluster.wait.aligned;"   ::: "memory");

    const int kq  = tid >> 6;               // 0..15, warp-uniform
    const int g2  = tid & 63;
    const int row = tid >> 5, u = tid & 31; // stage-2 mapping (tid<256)
    const int gu  = rank * 32 + u;
    float* seq_out = g_act[outIdx];

    const ulonglong2* wbase = (const ulonglong2*)Ws + g2;
    int ph = 0;                             // mbarrier phase parity

    for (int t = 0; t < TN; t++) {
        const int cur = t & 1, nxt = cur ^ 1;

        // ---- prefetch this step's gx into SMEM via cp.async (no regs held)
        if (tid < 256) {
            const float* g = g_gx + ((size_t)(bb + row) * TN + t) * GN + gu;
            unsigned d = gxbase + (unsigned)(tid * 16);
            cpa4(d     , g);
            cpa4(d + 4 , g + HN);
            cpa4(d + 8 , g + 2 * HN);
            cpa4(d + 12, g + 3 * HN);
            asm volatile("cp.async.commit_group;" ::: "memory");
        }

        // ---- wait for all peers' h(t-1) (64 arrivals); acquire cluster scope
        if (t) {
            unsigned done = 0;
            do {
                asm volatile(
                    "{\n\t.reg .pred P;\n\t"
                    "mbarrier.try_wait.parity.acquire.cluster.shared::cta.b64 P, [%1], %2, 0x989680;\n\t"
                    "selp.b32 %0, 1, 0, P;\n\t}"
                    : "=r"(done) : "r"(mbar), "r"(ph) : "memory");
            } while (!done);
            ph ^= 1;
        }

        // ---- matvec partial: gate rows {2g2, 2g2+1}, K slice [16kq, 16kq+16), 8 rows
        {
            const ulonglong2* hb = (const ulonglong2*)(hbuf + cur * 2048);
            ull a0[8] = {}, a1[8] = {};
            #pragma unroll
            for (int j = 0; j < 4; j++) {
                const int kk = kq * 4 + j;
                ulonglong2 w0 = wbase[(kk * 2    ) * 64];
                ulonglong2 w1 = wbase[(kk * 2 + 1) * 64];
                #pragma unroll
                for (int r = 0; r < 8; r++) {
                    ulonglong2 h = hb[r * 64 + kk];   // warp-broadcast
                    a0[r] = fma2(w0.x, h.x, a0[r]);
                    a0[r] = fma2(w0.y, h.y, a0[r]);
                    a1[r] = fma2(w1.x, h.x, a1[r]);
                    a1[r] = fma2(w1.y, h.y, a1[r]);
                }
            }
            #pragma unroll
            for (int r = 0; r < 8; r++) {
                float p0 = lo_f(a0[r]) + hi_f(a0[r]);
                float p1 = lo_f(a1[r]) + hi_f(a1[r]);
                ull pk = ((ull)__float_as_uint(p1) << 32) | (ull)__float_as_uint(p0);
                *(ull*)&pre[(kq * 8 + r) * 128 + 2 * g2] = pk;   // STS.64, dense
            }
        }
        __syncthreads();

        // ---- stage 2: reduce partials + activations + state + DSMEM broadcast
        if (tid < 256) {
            asm volatile("cp.async.wait_group 0;" ::: "memory");
            float4 gx4 = *(const float4*)&gxs[tid * 4];
            float gi = gx4.x, gf = gx4.y, gg = gx4.z, go = gx4.w;
            #pragma unroll
            for (int p = 0; p < 16; p++) {
                const float* pr = pre + (p * 8 + row) * 128;
                gi += pr[u];
                gf += pr[32 + u];
                gg += pr[64 + u];
                go += pr[96 + u];
            }

            float c = sigm(gf) * cst[tid] + sigm(gi) * tanh_f(gg);
            float h = sigm(go) * tanh_f(c);
            cst[tid] = c;

            seq_out[((size_t)(bb + row) * TN + t) * HN + gu] = h;

            // pack (h_u, h_{u+1}) in even lanes: one b64 remote store per CTA
            float hup = __shfl_down_sync(0xffffffffu, h, 1);
            if ((tid & 1) == 0) {
                ull hv = ((ull)__float_as_uint(hup) << 32) | (ull)__float_as_uint(h);
                unsigned off = (unsigned)((nxt * 2048 + row * HN + gu) * 4);
                #pragma unroll
                for (int d = 0; d < CL; d++) {
                    unsigned ra = mapa_u32(hbase, (unsigned)d) + off;
                    asm volatile("st.shared::cluster.b64 [%0], %1;"
                                 :: "r"(ra), "l"(hv) : "memory");
                }
            }
            __syncwarp();
            if ((tid & 31) == 0) {
                // publish this warp's stores cluster-wide, then arrive on all peers
                asm volatile("fence.acq_rel.cluster;" ::: "memory");
                #pragma unroll
                for (int d = 0; d < CL; d++) {
                    unsigned rb = mapa_u32(mbar, (unsigned)d);
                    asm volatile("mbarrier.arrive.shared::cluster.b64 _, [%0];"
                                 :: "r"(rb) : "memory");
                }
            }
        }
        __syncthreads();   // protects pre (rewritten next step) + gxs reuse
    }

    // exit safety: no CTA may leave while peers' remote stores could be in flight
    asm volatile("barrier.cluster.arrive.aligned;" ::: "memory");
    asm volatile("barrier.cluster.wait.aligned;"   ::: "memory");
}

// ---------------- final FC: out[b][o] = h_last[b] . fc_w[o] + fc_b[o] ----------------
__global__ void __launch_bounds__(256) fc_kernel(
    const float* __restrict__ fcw, const float* __restrict__ fcb,
    float* __restrict__ out)
{
    __shared__ float hs[HN];
    int b = blockIdx.x;
    const float* h = &g_act[(NL - 1) & 1][((size_t)b * TN + (TN - 1)) * HN];
    hs[threadIdx.x] = h[threadIdx.x];
    __syncthreads();
    if (threadIdx.x < ON) {
        int o = threadIdx.x;
        float s = fcb[o];
        #pragma unroll 8
        for (int u = 0; u < HN; u++) s += hs[u] * fcw[o * HN + u];
        out[b * ON + o] = s;
    }
}

// ---------------- launch ----------------
extern "C" void kernel_launch(void* const* d_in, const int* in_sizes, int n_in,
                              void* d_out, int out_size)
{
    (void)in_sizes; (void)n_in; (void)out_size;
    const float* x   = (const float*)d_in[0];
    const float* h0  = (const float*)d_in[1];
    const float* c0  = (const float*)d_in[2];
    const float* wih = (const float*)d_in[3];
    const float* whh = (const float*)d_in[4];
    const float* bih = (const float*)d_in[5];
    const float* bhh = (const float*)d_in[6];
    const float* fcw = (const float*)d_in[7];
    const float* fcb = (const float*)d_in[8];
    float* out = (float*)d_out;

    // idempotent, host-side, capture-safe
    cudaFuncSetAttribute(lstm_scan, cudaFuncAttributeMaxDynamicSharedMemorySize, SCAN_SMEM_BYTES);

    for (int l = 0; l < NL; l++) {
        const float* A = (l == 0) ? x : nullptr;
        int inIdx = (l == 0) ? 0 : ((l - 1) & 1);
        int lda   = (l == 0) ? IND : HN;
        dim3 grid(BN * TN / 128, GN / 64);
        gx_gemm<<<grid, 256>>>(A, inIdx, lda, lda,
                               wih + (size_t)l * GN * HN,
                               bih + (size_t)l * GN,
                               bhh + (size_t)l * GN);
        lstm_scan<<<128, 1024, SCAN_SMEM_BYTES>>>(
            whh + (size_t)l * GN * HN,
            h0  + (size_t)l * BN * HN,
            c0  + (size_t)l * BN * HN,
            l & 1);
    }
    fc_kernel<<<BN, 256>>>(fcw, fcb, out);
}

// round 14
// speedup vs baseline: 2.3468x; 1.1511x over previous
#include <cuda_runtime.h>
#include <cstdint>
#include <cstddef>

#define NL  6
#define HN  256
#define GN  1024
#define IND 128
#define BN  128
#define TN  512
#define ON  10
#define CL  8

typedef unsigned long long ull;

// ---------------- scratch (static device globals: allowed) ----------------
__device__ float g_gx[(size_t)BN * TN * GN];        // 256 MB: per-layer input-GEMM result
__device__ float g_act[2][(size_t)BN * TN * HN];    // 2 x 64 MB: layer activations ping-pong

// ---------------- helpers ----------------
__device__ __forceinline__ ull fma2(ull a, ull b, ull c) {
    ull d;
    asm("fma.rn.f32x2 %0, %1, %2, %3;" : "=l"(d) : "l"(a), "l"(b), "l"(c));
    return d;
}
__device__ __forceinline__ float lo_f(ull v){ return __uint_as_float((unsigned)(v & 0xffffffffull)); }
__device__ __forceinline__ float hi_f(ull v){ return __uint_as_float((unsigned)(v >> 32)); }

__device__ __forceinline__ float sigm(float x){ return 1.f / (1.f + __expf(-x)); }
__device__ __forceinline__ float tanh_f(float x){
    float ax = fabsf(x);
    float e  = __expf(2.f * ax);          // inf-safe: 2/inf -> 0 -> r=1
    float r  = 1.f - 2.f / (e + 1.f);
    return copysignf(r, x);
}
__device__ __forceinline__ unsigned cluster_rank(){
    unsigned r; asm("mov.u32 %0, %%cluster_ctarank;" : "=r"(r)); return r;
}
__device__ __forceinline__ unsigned mapa_u32(unsigned a, unsigned r){
    unsigned d; asm("mapa.shared::cluster.u32 %0, %1, %2;" : "=r"(d) : "r"(a), "r"(r)); return d;
}
__device__ __forceinline__ unsigned smem_u32(const void* p){
    return (unsigned)__cvta_generic_to_shared(p);
}
__device__ __forceinline__ void cpa4(unsigned dst, const float* src){
    asm volatile("cp.async.ca.shared.global [%0], [%1], 4;" :: "r"(dst), "l"(src) : "memory");
}

// ---------------- input GEMM: gx[m][n] = sum_k A[m][k]*Wih[n][k] + (bih[n]+bhh[n]) ----------------
__global__ void __launch_bounds__(256) gx_gemm(
    const float* __restrict__ Aext, int inIdx, int lda, int K,
    const float* __restrict__ W,              // [GN][HN] row stride HN always
    const float* __restrict__ bih, const float* __restrict__ bhh)
{
    const float* A = Aext ? Aext : g_act[inIdx];
    __shared__ ull As[128 * 9];               // 128 rows x 8 k-pairs, padded to 9
    __shared__ ull Bs[64 * 9];

    const int tid = threadIdx.x;
    const int m0 = blockIdx.x * 128;
    const int n0 = blockIdx.y * 64;
    const int tx = tid & 15;                  // n group
    const int ty = tid >> 4;                  // m group

    ull acc[8][4] = {};

    const int nchunk = K >> 4;
    for (int kb = 0; kb < nchunk; kb++) {
        {   // load A tile: 128 rows x 16 floats (8 ull). 2 threads/row, 4 ull each.
            int row  = tid >> 1;
            const float* ga = A + (size_t)(m0 + row) * lda + kb * 16 + (tid & 1) * 8;
            ull* dst = &As[row * 9 + (tid & 1) * 4];
            #pragma unroll
            for (int q = 0; q < 4; q++) dst[q] = *(const ull*)(ga + q * 2);
        }
        if (tid < 128) {  // load W tile: 64 rows x 16 floats
            int rw = tid >> 1;
            const float* gb = W + (size_t)(n0 + rw) * HN + kb * 16 + (tid & 1) * 8;
            ull* db = &Bs[rw * 9 + (tid & 1) * 4];
            #pragma unroll
            for (int q = 0; q < 4; q++) db[q] = *(const ull*)(gb + q * 2);
        }
        __syncthreads();

        #pragma unroll
        for (int kp = 0; kp < 8; kp++) {
            ull b2[4];
            #pragma unroll
            for (int j = 0; j < 4; j++) b2[j] = Bs[(tx + 16 * j) * 9 + kp];
            #pragma unroll
            for (int i = 0; i < 8; i++) {
                ull a2 = As[(ty + 16 * i) * 9 + kp];
                #pragma unroll
                for (int j = 0; j < 4; j++) acc[i][j] = fma2(a2, b2[j], acc[i][j]);
            }
        }
        __syncthreads();
    }

    #pragma unroll
    for (int j = 0; j < 4; j++) {
        int n = n0 + tx + 16 * j;
        float bias = bih[n] + bhh[n];
        #pragma unroll
        for (int i = 0; i < 8; i++) {
            int m = m0 + ty + 16 * i;
            g_gx[(size_t)m * GN + n] = lo_f(acc[i][j]) + hi_f(acc[i][j]) + bias;
        }
    }
}

// ---------------- recurrent scan (one launch per layer) ----------------
// 16 clusters x 8 CTAs, 512 threads/CTA. Cluster c owns batch rows [8c,8c+8).
// CTA rank r owns hidden units [32r,32r+32) -> 128 gate rows of W_hh, held
// ENTIRELY IN REGISTERS: thread (g2 = tid&63, kq = tid>>6) keeps gate rows
// {2g2, 2g2+1}, K-slice [32kq, 32kq+32) = 16 ulonglong2 = 64 registers.
// Per step:
//   - cp.async prefetch of this step's gx into SMEM (threads 0..255)
//   - mbarrier wait (count 64, phase parity): all peers' h(t-1) slices arrived
//   - matvec: pure register-FMA2; h read via warp-uniform broadcast LDS.128;
//     accumulators in two 4-row passes; 8 k-partials to pre[8][8][128]
//   - __syncthreads
//   - stage2 (tid<256): sum 8 partials + gx, activations, c/h update; h pairs
//     broadcast to all 8 CTAs via st.shared::cluster.b64; per-warp
//     fence.acq_rel.cluster + remote mbarrier arrive (8 warps x 8 CTAs = 64)
//   - __syncthreads
#define SCAN_H_F   4096                       // hbuf [2][8][256]
#define SCAN_P_F   8192                       // pre  [8 kq][8 row][128 gr]
#define SCAN_G_F   1024                       // gxs  [256 threads][4 gates]
#define SCAN_C_F   256                        // cst
#define SCAN_SMEM_FLOATS (SCAN_H_F + SCAN_P_F + SCAN_G_F + SCAN_C_F + 8)
#define SCAN_SMEM_BYTES  (SCAN_SMEM_FLOATS * 4)

__global__ void __cluster_dims__(CL, 1, 1) __launch_bounds__(512, 1)
lstm_scan(const float* __restrict__ whh,   // [GN][HN] for this layer
          const float* __restrict__ h0l,   // [BN][HN]
          const float* __restrict__ c0l,   // [BN][HN]
          int outIdx)
{
    extern __shared__ float sm[];
    float* hbuf = sm;                                   // [2][8][256]
    float* pre  = hbuf + SCAN_H_F;                      // [8][8][128]
    float* gxs  = pre + SCAN_P_F;                       // [256][4]
    float* cst  = gxs + SCAN_G_F;                       // [256]
    const unsigned mbar = smem_u32(cst + SCAN_C_F);     // 8B aligned
    const unsigned hbase = smem_u32(hbuf);
    const unsigned gxbase = smem_u32(gxs);

    const int tid   = threadIdx.x;
    const unsigned rank = cluster_rank();   // 0..7
    const int bb    = (blockIdx.x >> 3) * 8;            // first batch row

    const int g2  = tid & 63;               // gate-row pair
    const int kq  = tid >> 6;               // 0..7, warp-uniform
    const int row = tid >> 5, u = tid & 31; // stage-2 mapping (tid<256)
    const int gu  = rank * 32 + u;

    // ---- init mbarrier (count = 8 warps x 8 CTAs = 64 arrivals per step)
    if (tid == 0)
        asm volatile("mbarrier.init.shared.b64 [%0], %1;" :: "r"(mbar), "r"(64) : "memory");

    // ---- load this thread's W slice into REGISTERS (loop-invariant)
    // gate rows gr = 2*g2 + r2; global row = (gr>>5)*HN + rank*32 + (gr&31);
    // K columns [32*kq, 32*kq+32) -> 8 ulonglong2 per row.
    ulonglong2 W0[8], W1[8];
    {
        int gr0 = 2 * g2,     q0 = gr0 >> 5, ul0 = gr0 & 31;
        int gr1 = 2 * g2 + 1, q1 = gr1 >> 5, ul1 = gr1 & 31;
        const float* w0p = whh + (size_t)(q0 * HN + rank * 32 + ul0) * HN + kq * 32;
        const float* w1p = whh + (size_t)(q1 * HN + rank * 32 + ul1) * HN + kq * 32;
        #pragma unroll
        for (int kk = 0; kk < 8; kk++) {
            W0[kk] = *(const ulonglong2*)(w0p + kk * 4);
            W1[kk] = *(const ulonglong2*)(w1p + kk * 4);
        }
    }

    // ---- init h (buffer 0), c
    for (int li = tid; li < 8 * HN; li += 512)
        hbuf[li] = h0l[(size_t)(bb + (li >> 8)) * HN + (li & 255)];
    if (tid < 256)
        cst[tid] = c0l[(size_t)(bb + row) * HN + gu];
    __syncthreads();
    // cluster sync: all mbarriers initialized before any remote arrive can land
    asm volatile("barrier.cluster.arrive.aligned;" ::: "memory");
    asm volatile("barrier.cluster.wait.aligned;"   ::: "memory");

    float* seq_out = g_act[outIdx];
    int ph = 0;                             // mbarrier phase parity

    for (int t = 0; t < TN; t++) {
        const int cur = t & 1, nxt = cur ^ 1;

        // ---- prefetch this step's gx into SMEM via cp.async (no regs held)
        if (tid < 256) {
            const float* g = g_gx + ((size_t)(bb + row) * TN + t) * GN + gu;
            unsigned d = gxbase + (unsigned)(tid * 16);
            cpa4(d     , g);
            cpa4(d + 4 , g + HN);
            cpa4(d + 8 , g + 2 * HN);
            cpa4(d + 12, g + 3 * HN);
            asm volatile("cp.async.commit_group;" ::: "memory");
        }

        // ---- wait for all peers' h(t-1) (64 arrivals); acquire cluster scope
        if (t) {
            unsigned done = 0;
            do {
                asm volatile(
                    "{\n\t.reg .pred P;\n\t"
                    "mbarrier.try_wait.parity.acquire.cluster.shared::cta.b64 P, [%1], %2, 0x989680;\n\t"
                    "selp.b32 %0, 1, 0, P;\n\t}"
                    : "=r"(done) : "r"(mbar), "r"(ph) : "memory");
            } while (!done);
            ph ^= 1;
        }

        // ---- matvec: register weights, broadcast h; two 4-row passes
        {
            const ulonglong2* hb = (const ulonglong2*)(hbuf + cur * 2048) + kq * 8;
            #pragma unroll
            for (int pass = 0; pass < 2; pass++) {
                ull a0[4] = {}, a1[4] = {};
                const ulonglong2* hp = hb + pass * 4 * 64;
                #pragma unroll
                for (int kk = 0; kk < 8; kk++) {
                    ulonglong2 w0 = W0[kk], w1 = W1[kk];
                    #pragma unroll
                    for (int r = 0; r < 4; r++) {
                        ulonglong2 h = hp[r * 64 + kk];   // warp-uniform broadcast
                        a0[r] = fma2(w0.x, h.x, a0[r]);
                        a0[r] = fma2(w0.y, h.y, a0[r]);
                        a1[r] = fma2(w1.x, h.x, a1[r]);
                        a1[r] = fma2(w1.y, h.y, a1[r]);
                    }
                }
                #pragma unroll
                for (int r = 0; r < 4; r++) {
                    float p0 = lo_f(a0[r]) + hi_f(a0[r]);
                    float p1 = lo_f(a1[r]) + hi_f(a1[r]);
                    ull pk = ((ull)__float_as_uint(p1) << 32) | (ull)__float_as_uint(p0);
                    *(ull*)&pre[(kq * 8 + pass * 4 + r) * 128 + 2 * g2] = pk;  // STS.64
                }
            }
        }
        __syncthreads();

        // ---- stage 2: reduce partials + activations + state + DSMEM broadcast
        if (tid < 256) {
            asm volatile("cp.async.wait_group 0;" ::: "memory");
            float4 gx4 = *(const float4*)&gxs[tid * 4];
            float gi = gx4.x, gf = gx4.y, gg = gx4.z, go = gx4.w;
            #pragma unroll
            for (int p = 0; p < 8; p++) {
                const float* pr = pre + (p * 8 + row) * 128;
                gi += pr[u];
                gf += pr[32 + u];
                gg += pr[64 + u];
                go += pr[96 + u];
            }

            float c = sigm(gf) * cst[tid] + sigm(gi) * tanh_f(gg);
            float h = sigm(go) * tanh_f(c);

            // pack (h_u, h_{u+1}) in even lanes: one b64 remote store per CTA
            float hup = __shfl_down_sync(0xffffffffu, h, 1);
            if ((tid & 1) == 0) {
                ull hv = ((ull)__float_as_uint(hup) << 32) | (ull)__float_as_uint(h);
                unsigned off = (unsigned)((nxt * 2048 + row * HN + gu) * 4);
                #pragma unroll
                for (int d = 0; d < CL; d++) {
                    unsigned ra = mapa_u32(hbase, (unsigned)d) + off;
                    asm volatile("st.shared::cluster.b64 [%0], %1;"
                                 :: "r"(ra), "l"(hv) : "memory");
                }
            }
            __syncwarp();
            if ((tid & 31) == 0) {
                // publish this warp's stores cluster-wide, then arrive on all peers
                asm volatile("fence.acq_rel.cluster;" ::: "memory");
                #pragma unroll
                for (int d = 0; d < CL; d++) {
                    unsigned rb = mapa_u32(mbar, (unsigned)d);
                    asm volatile("mbarrier.arrive.shared::cluster.b64 _, [%0];"
                                 :: "r"(rb) : "memory");
                }
            }
            // off the cluster critical path:
            cst[tid] = c;
            seq_out[((size_t)(bb + row) * TN + t) * HN + gu] = h;
        }
        __syncthreads();   // protects pre + gxs for the next step
    }

    // exit safety: no CTA may leave while peers' remote stores could be in flight
    asm volatile("barrier.cluster.arrive.aligned;" ::: "memory");
    asm volatile("barrier.cluster.wait.aligned;"   ::: "memory");
}

// ---------------- final FC: out[b][o] = h_last[b] . fc_w[o] + fc_b[o] ----------------
__global__ void __launch_bounds__(256) fc_kernel(
    const float* __restrict__ fcw, const float* __restrict__ fcb,
    float* __restrict__ out)
{
    __shared__ float hs[HN];
    int b = blockIdx.x;
    const float* h = &g_act[(NL - 1) & 1][((size_t)b * TN + (TN - 1)) * HN];
    hs[threadIdx.x] = h[threadIdx.x];
    __syncthreads();
    if (threadIdx.x < ON) {
        int o = threadIdx.x;
        float s = fcb[o];
        #pragma unroll 8
        for (int u = 0; u < HN; u++) s += hs[u] * fcw[o * HN + u];
        out[b * ON + o] = s;
    }
}

// ---------------- launch ----------------
extern "C" void kernel_launch(void* const* d_in, const int* in_sizes, int n_in,
                              void* d_out, int out_size)
{
    (void)in_sizes; (void)n_in; (void)out_size;
    const float* x   = (const float*)d_in[0];
    const float* h0  = (const float*)d_in[1];
    const float* c0  = (const float*)d_in[2];
    const float* wih = (const float*)d_in[3];
    const float* whh = (const float*)d_in[4];
    const float* bih = (const float*)d_in[5];
    const float* bhh = (const float*)d_in[6];
    const float* fcw = (const float*)d_in[7];
    const float* fcb = (const float*)d_in[8];
    float* out = (float*)d_out;

    // idempotent, host-side, capture-safe
    cudaFuncSetAttribute(lstm_scan, cudaFuncAttributeMaxDynamicSharedMemorySize, SCAN_SMEM_BYTES);

    for (int l = 0; l < NL; l++) {
        const float* A = (l == 0) ? x : nullptr;
        int inIdx = (l == 0) ? 0 : ((l - 1) & 1);
        int lda   = (l == 0) ? IND : HN;
        dim3 grid(BN * TN / 128, GN / 64);
        gx_gemm<<<grid, 256>>>(A, inIdx, lda, lda,
                               wih + (size_t)l * GN * HN,
                               bih + (size_t)l * GN,
                               bhh + (size_t)l * GN);
        lstm_scan<<<128, 512, SCAN_SMEM_BYTES>>>(
            whh + (size_t)l * GN * HN,
            h0  + (size_t)l * BN * HN,
            c0  + (size_t)l * BN * HN,
            l & 1);
    }
    fc_kernel<<<BN, 256>>>(fcw, fcb, out);
}